// round 15
// baseline (speedup 1.0000x reference)
#include <cuda_runtime.h>
#include <cuda_fp16.h>
#include <cstdint>

#define NB 32
#define NL 512
#define ND 512
#define NH 8
#define NDH 64
#define MTOT (NB*NL)

typedef unsigned int u32;

// ---------------- scratch (static device memory; no allocs allowed) ----------
__device__ u32 g_Xq[(size_t)MTOT * ND / 2];     // fp16 inputs (queries)
__device__ u32 g_Xk[(size_t)MTOT * ND / 2];     // fp16 inputs (keys)
__device__ u32 g_Wh[3][(size_t)ND * ND / 2];    // fp16 weights (Wq,Wk,Wv)
__device__ uint4 g_Qh[(size_t)MTOT * ND / 8];   // fp16 projected Q
__device__ uint4 g_Kh[(size_t)MTOT * ND / 8];
__device__ uint4 g_Vh[(size_t)MTOT * ND / 8];
__device__ float g_qm[MTOT];
__device__ float g_km[MTOT];
__device__ u32   g_Eu[(size_t)NB * NH * NL * 256];   // unnormalized E, fp16x2

#define CSCALE 0.18033688011112042f   /* (1/8) * log2(e) */

// ---------------- helpers ----------------------------------------------------
__device__ __forceinline__ float ex2(float x) {
    float y;
    asm("ex2.approx.ftz.f32 %0, %1;" : "=f"(y) : "f"(x));
    return y;
}
__device__ __forceinline__ u32 pack2(float lo, float hi) {
    u32 r;
    asm("cvt.rn.f16x2.f32 %0, %1, %2;" : "=r"(r) : "f"(hi), "f"(lo));
    return r;
}
__device__ __forceinline__ void mma16(float c[4], const u32 a[4], u32 b0, u32 b1) {
    asm volatile(
        "mma.sync.aligned.m16n8k16.row.col.f32.f16.f16.f32 "
        "{%0,%1,%2,%3},{%4,%5,%6,%7},{%8,%9},{%0,%1,%2,%3};\n"
        : "+f"(c[0]), "+f"(c[1]), "+f"(c[2]), "+f"(c[3])
        : "r"(a[0]), "r"(a[1]), "r"(a[2]), "r"(a[3]), "r"(b0), "r"(b1));
}
__device__ __forceinline__ void ldsm4(u32 r[4], u32 a) {
    asm volatile("ldmatrix.sync.aligned.m8n8.x4.shared.b16 {%0,%1,%2,%3},[%4];"
                 : "=r"(r[0]), "=r"(r[1]), "=r"(r[2]), "=r"(r[3]) : "r"(a));
}
__device__ __forceinline__ void ldsm4t(u32 r[4], u32 a) {
    asm volatile("ldmatrix.sync.aligned.m8n8.x4.trans.shared.b16 {%0,%1,%2,%3},[%4];"
                 : "=r"(r[0]), "=r"(r[1]), "=r"(r[2]), "=r"(r[3]) : "r"(a));
}
__device__ __forceinline__ u32 sptr(const void* p) {
    return (u32)__cvta_generic_to_shared(p);
}
__device__ __forceinline__ void cpa16(u32 dst, const void* src) {
    asm volatile("cp.async.cg.shared.global [%0],[%1],16;" :: "r"(dst), "l"(src));
}
#define CPA_COMMIT() asm volatile("cp.async.commit_group;")
#define CPA_WAIT(N)  asm volatile("cp.async.wait_group %0;" :: "n"(N))

// ---------------- kernel 0a: fp32 -> fp16 inputs + sign masks ----------------
__global__ __launch_bounds__(256) void cvt_inputs(
    const float* __restrict__ q, const float* __restrict__ k) {
    const int wid = threadIdx.x >> 5, lane = threadIdx.x & 31;
    const int row = blockIdx.x * 8 + wid;
    const float* src = blockIdx.y ? k : q;
    u32* dst = blockIdx.y ? g_Xk : g_Xq;
    float* mdst = blockIdx.y ? g_km : g_qm;

    const float4* s4 = reinterpret_cast<const float4*>(src + (size_t)row * ND);
    uint2* d2 = reinterpret_cast<uint2*>(dst + (size_t)row * ND / 2);
    float s = 0.f;
#pragma unroll
    for (int i = 0; i < 4; i++) {
        float4 v = s4[lane + 32 * i];
        s += fabsf(v.x) + fabsf(v.y) + fabsf(v.z) + fabsf(v.w);
        d2[lane + 32 * i] = make_uint2(pack2(v.x, v.y), pack2(v.z, v.w));
    }
#pragma unroll
    for (int o = 16; o; o >>= 1) s += __shfl_xor_sync(0xffffffffu, s, o);
    if (lane == 0) mdst[row] = s > 0.f ? 1.f : 0.f;
}

// ---------------- kernel 0b: fp32 -> fp16 weights ----------------------------
__global__ __launch_bounds__(128) void cvt_w(
    const float* __restrict__ Wq, const float* __restrict__ Wk,
    const float* __restrict__ Wv) {
    const int which = blockIdx.y;
    const float* W = (which == 0) ? Wq : (which == 1) ? Wk : Wv;
    const int row = blockIdx.x, c = threadIdx.x * 4;
    float4 v = *reinterpret_cast<const float4*>(W + (size_t)row * ND + c);
    *reinterpret_cast<uint2*>(&g_Wh[which][((size_t)row * ND + c) >> 1]) =
        make_uint2(pack2(v.x, v.y), pack2(v.z, v.w));
}

// ---------------- kernel 1: fp16 projection GEMMs (3-stage cp.async) ---------
#define PROJ_SMEM (3 * 2 * 128 * 64 * 2)   // 96KB

__global__ __launch_bounds__(256, 2) void proj_kernel(
    const float* __restrict__ bq, const float* __restrict__ bk,
    const float* __restrict__ bv) {
    extern __shared__ char smem_raw[];
    u32* sAu = reinterpret_cast<u32*>(smem_raw);   // [3][4096] u32
    u32* sBu = sAu + 12288;                         // [3][4096] u32
    const u32 sA0 = sptr(sAu), sB0 = sptr(sBu);

    const int which = blockIdx.z;
    const u32* X    = (which == 0) ? g_Xq : g_Xk;
    const u32* Wt   = g_Wh[which];
    const float* bias = (which == 0) ? bq : (which == 1) ? bk : bv;
    u32* out = reinterpret_cast<u32*>((which == 0) ? g_Qh : (which == 1) ? g_Kh : g_Vh);

    const int tid = threadIdx.x, wid = tid >> 5, lane = tid & 31;
    const int g = lane >> 2, tg = lane & 3;
    const int wm = (wid >> 2) * 64, wn = (wid & 3) * 32;
    const int m0 = blockIdx.y * 128, n0 = blockIdx.x * 128;
    const int l7 = lane & 7, mat = lane >> 3;

    auto stage = [&](int buf, int kb) {
#pragma unroll
        for (int j = 0; j < 4; j++) {
            int idx = tid + 256 * j;
            int r = idx >> 3, c = idx & 7;
            u32 off = (u32)(buf * 16384 + (r * 32 + ((c ^ (r & 7)) * 4)) * 4);  // bytes
            cpa16(sA0 + off, X  + (((size_t)(m0 + r) * ND + kb) >> 1) + c * 4);
            cpa16(sB0 + off, Wt + (((size_t)(n0 + r) * ND + kb) >> 1) + c * 4);
        }
    };

    float acc[4][4][4];
#pragma unroll
    for (int mi = 0; mi < 4; mi++)
#pragma unroll
        for (int ni = 0; ni < 4; ni++)
#pragma unroll
            for (int e = 0; e < 4; e++) acc[mi][ni][e] = 0.f;

    stage(0, 0);
    CPA_COMMIT();
    stage(1, 64);
    CPA_COMMIT();

    for (int it = 0; it < 8; it++) {
        const int buf = it % 3;
        if (it == 7) { CPA_WAIT(0); } else { CPA_WAIT(1); }
        __syncthreads();
        if (it + 2 < 8) {
            stage((it + 2) % 3, (it + 2) * 64);
            CPA_COMMIT();
        }

#pragma unroll
        for (int ks = 0; ks < 4; ks++) {
            u32 af[4][4], bf[2][4];
#pragma unroll
            for (int mi = 0; mi < 4; mi++) {
                int row = wm + mi * 16 + (mat & 1) * 8 + l7;
                int chunk = 2 * ks + (mat >> 1);
                ldsm4(af[mi], sA0 + buf * 16384 + row * 128 + ((chunk ^ l7) << 4));
            }
#pragma unroll
            for (int np = 0; np < 2; np++) {
                int nb = (wn >> 3) + 2 * np + (mat >> 1);
                int row = nb * 8 + l7;
                int chunk = 2 * ks + (mat & 1);
                ldsm4(bf[np], sB0 + buf * 16384 + row * 128 + ((chunk ^ l7) << 4));
            }
#pragma unroll
            for (int mi = 0; mi < 4; mi++)
#pragma unroll
                for (int ni = 0; ni < 4; ni++)
                    mma16(acc[mi][ni], af[mi], bf[ni >> 1][(ni & 1) * 2], bf[ni >> 1][(ni & 1) * 2 + 1]);
        }
    }

#pragma unroll
    for (int mi = 0; mi < 4; mi++) {
#pragma unroll
        for (int ni = 0; ni < 4; ni++) {
            int row = m0 + wm + mi * 16 + g;
            int col = n0 + wn + ni * 8 + 2 * tg;
            float2 bv2 = *reinterpret_cast<const float2*>(bias + col);
            out[((size_t)row * ND + col) >> 1] =
                pack2(acc[mi][ni][0] + bv2.x, acc[mi][ni][1] + bv2.y);
            out[((size_t)(row + 8) * ND + col) >> 1] =
                pack2(acc[mi][ni][2] + bv2.x, acc[mi][ni][3] + bv2.y);
        }
    }
}

// ---------------- kernel 2: fp16 flash attention + fused weight normalize ----
// smem: sQ 16KB + sK 16KB + sV 16KB + km 512B + linv 512B; 3 CTAs/SM (RF-bound)
#define ATTN_SMEM (3 * 8192 * 2 + 256 * 4)

__global__ __launch_bounds__(128, 3) void attn_kernel(
    const int* __restrict__ causality, float* __restrict__ outp,
    float* __restrict__ attnp) {
    extern __shared__ char smem_raw[];
    u32* sQu = reinterpret_cast<u32*>(smem_raw);
    u32* sKu = sQu + 4096;
    u32* sVu = sKu + 4096;
    float* sKM  = reinterpret_cast<float*>(sVu + 4096);   // 128
    float* sLin = sKM + 128;                               // 128
    const u32 sQ0 = sptr(sQu), sK0 = sptr(sKu), sV0 = sptr(sVu);

    const int qt = 3 - blockIdx.x;          // heavy causal tiles launch first
    const int h = blockIdx.y, b = blockIdx.z;
    const int tid = threadIdx.x, wid = tid >> 5, lane = tid & 31;
    const int g = lane >> 2, tg = lane & 3;
    const int l7 = lane & 7, mat = lane >> 3;
    const int causal = *causality;
    const int q0 = qt * 128;
    const int wm = wid * 32;                // warp owns 32 q-rows

    // ---- stage Q (128 threads, 8 uint4 each) ----
    {
        const uint4* qsrc = g_Qh + (((size_t)(b * NL + q0) * ND + h * NDH) >> 3);
#pragma unroll
        for (int j = 0; j < 8; j++) {
            int idx = tid + 128 * j;
            int r = idx >> 3, c = idx & 7;
            *reinterpret_cast<uint4*>(sQu + r * 32 + ((c ^ (r & 7)) * 4)) = qsrc[r * 64 + c];
        }
    }
    __syncthreads();

    // ---- hoisted Q A-fragments: 2 m-blocks x 4 k-steps ----
    u32 aq[2][4][4];
#pragma unroll
    for (int mb = 0; mb < 2; mb++)
#pragma unroll
        for (int ks = 0; ks < 4; ks++) {
            int row = wm + mb * 16 + (mat & 1) * 8 + l7;
            int chunk = 2 * ks + (mat >> 1);
            ldsm4(aq[mb][ks], sQ0 + row * 128 + ((chunk ^ l7) << 4));
        }

    // per-thread row identities: rows[mb*2 + r] = wm + mb*16 + r*8 + g
    int rowg[4];
    float qm[4];
#pragma unroll
    for (int i = 0; i < 4; i++) {
        rowg[i] = q0 + wm + (i >> 1) * 16 + (i & 1) * 8 + g;
        qm[i] = g_qm[b * NL + rowg[i]];
    }

    float lrun[4] = {0.f, 0.f, 0.f, 0.f};
    const int ktmax = causal ? qt : 3;
    const int wrowmax = q0 + wm + 31;       // warp's max global row (chunk skip)

    float oacc[2][8][4];
#pragma unroll
    for (int mb = 0; mb < 2; mb++)
#pragma unroll
        for (int ni = 0; ni < 8; ni++)
#pragma unroll
            for (int e = 0; e < 4; e++) oacc[mb][ni][e] = 0.f;

    // E scratch row pointers (row = rowg[mb*2], second row at +8*256)
    u32* erow[2];
#pragma unroll
    for (int mb = 0; mb < 2; mb++)
        erow[mb] = g_Eu + ((size_t)(b * NH + h) * NL + rowg[mb * 2]) * 256 + tg;

    for (int kt = 0; kt <= ktmax; kt++) {
        __syncthreads();
        {
            const uint4* kbase = g_Kh + (((size_t)(b * NL + kt * 128) * ND + h * NDH) >> 3);
            const uint4* vbase = g_Vh + (((size_t)(b * NL + kt * 128) * ND + h * NDH) >> 3);
#pragma unroll
            for (int j = 0; j < 8; j++) {
                int idx = tid + 128 * j;
                int r = idx >> 3, c = idx & 7;
                int off = r * 32 + ((c ^ (r & 7)) * 4);
                *reinterpret_cast<uint4*>(sKu + off) = kbase[r * 64 + c];
                *reinterpret_cast<uint4*>(sVu + off) = vbase[r * 64 + c];
            }
            sKM[tid] = g_km[b * NL + kt * 128 + tid];
        }
        __syncthreads();

#pragma unroll
        for (int hf = 0; hf < 2; hf++) {
#pragma unroll
            for (int c = 0; c < 4; c++) {     // 16 kv cols per chunk
                // diagonal-tile chunk skip: entire 16-col window above warp rows
                if (causal && kt == ktmax && (kt * 128 + hf * 64 + c * 16) > wrowmax)
                    continue;

                // ---- S chunk = Q K^T ----
                float acc[2][2][4];
#pragma unroll
                for (int mb = 0; mb < 2; mb++)
#pragma unroll
                    for (int nb = 0; nb < 2; nb++)
#pragma unroll
                        for (int e = 0; e < 4; e++) acc[mb][nb][e] = 0.f;
#pragma unroll
                for (int ks = 0; ks < 4; ks++) {
                    u32 kb4[4];
                    int row = 64 * hf + (2 * c + (mat >> 1)) * 8 + l7;
                    int chunk = 2 * ks + (mat & 1);
                    ldsm4(kb4, sK0 + row * 128 + ((chunk ^ l7) << 4));
#pragma unroll
                    for (int mb = 0; mb < 2; mb++) {
                        mma16(acc[mb][0], aq[mb][ks], kb4[0], kb4[1]);
                        mma16(acc[mb][1], aq[mb][ks], kb4[2], kb4[3]);
                    }
                }

                // ---- mask, exp2, rowsum, pack, E store ----
                u32 ef[2][4];
#pragma unroll
                for (int mb = 0; mb < 2; mb++) {
#pragma unroll
                    for (int nb = 0; nb < 2; nb++) {
                        int cl = (c * 2 + nb) * 8 + 2 * tg;
                        int cg = kt * 128 + hf * 64 + cl;
                        float km0 = sKM[hf * 64 + cl], km1 = sKM[hf * 64 + cl + 1];
                        float m00 = (causal && (cg     > rowg[mb * 2]))     ? 0.f : km0;
                        float m01 = (causal && (cg + 1 > rowg[mb * 2]))     ? 0.f : km1;
                        float m10 = (causal && (cg     > rowg[mb * 2 + 1])) ? 0.f : km0;
                        float m11 = (causal && (cg + 1 > rowg[mb * 2 + 1])) ? 0.f : km1;
                        float e00 = ex2(fminf(acc[mb][nb][0] * CSCALE, 15.f)) * m00;
                        float e01 = ex2(fminf(acc[mb][nb][1] * CSCALE, 15.f)) * m01;
                        float e10 = ex2(fminf(acc[mb][nb][2] * CSCALE, 15.f)) * m10;
                        float e11 = ex2(fminf(acc[mb][nb][3] * CSCALE, 15.f)) * m11;
                        lrun[mb * 2]     += e00 + e01;
                        lrun[mb * 2 + 1] += e10 + e11;
                        ef[mb][nb * 2]     = pack2(e00, e01);
                        ef[mb][nb * 2 + 1] = pack2(e10, e11);
                    }
                    if (attnp) {
                        u32* e0 = erow[mb] + kt * 64 + hf * 32 + c * 8;
                        e0[0] = ef[mb][0];
                        e0[4] = ef[mb][2];
                        e0[8 * 256]     = ef[mb][1];
                        e0[8 * 256 + 4] = ef[mb][3];
                    }
                }

                // ---- O += E_chunk * V_chunk ----
#pragma unroll
                for (int np = 0; np < 4; np++) {
                    u32 vb4[4];
                    int nb = 2 * np + (mat >> 1);
                    int row = 64 * hf + 16 * c + (mat & 1) * 8 + l7;
                    ldsm4t(vb4, sV0 + row * 128 + ((nb ^ l7) << 4));
#pragma unroll
                    for (int mb = 0; mb < 2; mb++) {
                        mma16(oacc[mb][2 * np],     ef[mb], vb4[0], vb4[1]);
                        mma16(oacc[mb][2 * np + 1], ef[mb], vb4[2], vb4[3]);
                    }
                }
            }
        }
    }

    // reduce partial row-sums across the 4 tg lane-groups
#pragma unroll
    for (int i = 0; i < 4; i++) {
        lrun[i] += __shfl_xor_sync(0xffffffffu, lrun[i], 1);
        lrun[i] += __shfl_xor_sync(0xffffffffu, lrun[i], 2);
    }

    float invl[4];
#pragma unroll
    for (int i = 0; i < 4; i++)
        invl[i] = lrun[i] > 0.f ? qm[i] / lrun[i] : 0.f;
    if (tg == 0) {
#pragma unroll
        for (int i = 0; i < 4; i++)
            sLin[rowg[i] - q0] = invl[i];
    }

    // ---- O epilogue ----
#pragma unroll
    for (int mb = 0; mb < 2; mb++) {
#pragma unroll
        for (int ni = 0; ni < 8; ni++) {
            int col = h * NDH + ni * 8 + 2 * tg;
            *reinterpret_cast<float2*>(outp + ((size_t)b * NL + rowg[mb * 2]) * ND + col) =
                make_float2(oacc[mb][ni][0] * invl[mb * 2], oacc[mb][ni][1] * invl[mb * 2]);
            *reinterpret_cast<float2*>(outp + ((size_t)b * NL + rowg[mb * 2 + 1]) * ND + col) =
                make_float2(oacc[mb][ni][2] * invl[mb * 2 + 1], oacc[mb][ni][3] * invl[mb * 2 + 1]);
        }
    }

    // ---- fused weight normalization: read own fp16 E rows (L2-hot), scale,
    //      stream fp32 weights; zero-fill causal region without reading ----
    if (attnp) {
        __threadfence_block();
        __syncthreads();   // sLin + all E STGs ordered before re-read
        const u32* ebase = g_Eu + ((size_t)(b * NH + h) * NL + q0) * 256;
        float* wbase = attnp + ((size_t)(b * NH + h) * NL + q0) * NL;
        const float4 z4 = make_float4(0.f, 0.f, 0.f, 0.f);
        for (int pass = 0; pass < 32; pass++) {
            int row = pass * 4 + wid;      // warp per row, coalesced along cols
            float li = sLin[row];
            int rowgl = q0 + row;
            const uint2* es = reinterpret_cast<const uint2*>(ebase + (size_t)row * 256);
            float4* ob = reinterpret_cast<float4*>(wbase + (size_t)row * NL);
#pragma unroll
            for (int jj = 0; jj < 4; jj++) {
                int c4 = lane + 32 * jj;
                int col = c4 * 4;
                float4 o;
                if (causal && col > rowgl) {
                    o = z4;                // never-written / masked: no read
                } else {
                    uint2 e = es[c4];
                    float2 lo = __half22float2(*reinterpret_cast<__half2*>(&e.x));
                    float2 hi = __half22float2(*reinterpret_cast<__half2*>(&e.y));
                    o = make_float4(lo.x * li, lo.y * li, hi.x * li, hi.y * li);
                }
                ob[c4] = o;
            }
        }
    }
}

// ---------------- launcher ----------------------------------------------------
extern "C" void kernel_launch(void* const* d_in, const int* in_sizes, int n_in,
                              void* d_out, int out_size) {
    (void)in_sizes; (void)n_in;
    const float* queries = (const float*)d_in[0];
    const float* keys    = (const float*)d_in[1];
    const float* Wq = (const float*)d_in[2];
    const float* bq = (const float*)d_in[3];
    const float* Wk = (const float*)d_in[4];
    const float* bk = (const float*)d_in[5];
    const float* Wv = (const float*)d_in[6];
    const float* bv = (const float*)d_in[7];
    const int* caus = (const int*)d_in[8];

    float* outp = (float*)d_out;
    const size_t o_elems = (size_t)NB * NL * ND;
    const size_t a_elems = (size_t)NB * NH * NL * NL;
    float* attnp = ((size_t)out_size >= o_elems + a_elems) ? (outp + o_elems) : nullptr;

    cudaFuncSetAttribute(proj_kernel, cudaFuncAttributeMaxDynamicSharedMemorySize, PROJ_SMEM);
    cudaFuncSetAttribute(attn_kernel, cudaFuncAttributeMaxDynamicSharedMemorySize, ATTN_SMEM);

    cvt_inputs<<<dim3(MTOT / 8, 2), 256>>>(queries, keys);
    cvt_w<<<dim3(ND, 3), 128>>>(Wq, Wk, Wv);
    proj_kernel<<<dim3(4, 128, 3), 256, PROJ_SMEM>>>(bq, bk, bv);
    attn_kernel<<<dim3(4, NH, NB), 128, ATTN_SMEM>>>(caus, outp, attnp);
}

// round 16
// speedup vs baseline: 1.2731x; 1.2731x over previous
#include <cuda_runtime.h>
#include <cuda_fp16.h>
#include <cstdint>

#define NB 32
#define NL 512
#define ND 512
#define NH 8
#define NDH 64
#define MTOT (NB*NL)

typedef unsigned int u32;

// ---------------- scratch (static device memory; no allocs allowed) ----------
__device__ u32 g_Xq[(size_t)MTOT * ND / 2];     // fp16 inputs (queries)
__device__ u32 g_Xk[(size_t)MTOT * ND / 2];     // fp16 inputs (keys)
__device__ u32 g_Wh[3][(size_t)ND * ND / 2];    // fp16 weights (Wq,Wk,Wv)
__device__ uint4 g_Qh[(size_t)MTOT * ND / 8];   // fp16 projected Q
__device__ uint4 g_Kh[(size_t)MTOT * ND / 8];
__device__ uint4 g_Vh[(size_t)MTOT * ND / 8];
__device__ float g_qm[MTOT];
__device__ float g_km[MTOT];
__device__ float g_linv[NB * NH * NL];
__device__ u32   g_Eu[(size_t)NB * NH * NL * 256];   // unnormalized E, fp16x2

#define CSCALE 0.18033688011112042f   /* (1/8) * log2(e) */

// ---------------- helpers ----------------------------------------------------
__device__ __forceinline__ float ex2(float x) {
    float y;
    asm("ex2.approx.ftz.f32 %0, %1;" : "=f"(y) : "f"(x));
    return y;
}
__device__ __forceinline__ u32 pack2(float lo, float hi) {
    u32 r;
    asm("cvt.rn.f16x2.f32 %0, %1, %2;" : "=r"(r) : "f"(hi), "f"(lo));
    return r;
}
__device__ __forceinline__ void mma16(float c[4], const u32 a[4], u32 b0, u32 b1) {
    asm volatile(
        "mma.sync.aligned.m16n8k16.row.col.f32.f16.f16.f32 "
        "{%0,%1,%2,%3},{%4,%5,%6,%7},{%8,%9},{%0,%1,%2,%3};\n"
        : "+f"(c[0]), "+f"(c[1]), "+f"(c[2]), "+f"(c[3])
        : "r"(a[0]), "r"(a[1]), "r"(a[2]), "r"(a[3]), "r"(b0), "r"(b1));
}
__device__ __forceinline__ void ldsm4(u32 r[4], u32 a) {
    asm volatile("ldmatrix.sync.aligned.m8n8.x4.shared.b16 {%0,%1,%2,%3},[%4];"
                 : "=r"(r[0]), "=r"(r[1]), "=r"(r[2]), "=r"(r[3]) : "r"(a));
}
__device__ __forceinline__ void ldsm4t(u32 r[4], u32 a) {
    asm volatile("ldmatrix.sync.aligned.m8n8.x4.trans.shared.b16 {%0,%1,%2,%3},[%4];"
                 : "=r"(r[0]), "=r"(r[1]), "=r"(r[2]), "=r"(r[3]) : "r"(a));
}
__device__ __forceinline__ u32 sptr(const void* p) {
    return (u32)__cvta_generic_to_shared(p);
}
__device__ __forceinline__ void cpa16(u32 dst, const void* src) {
    asm volatile("cp.async.cg.shared.global [%0],[%1],16;" :: "r"(dst), "l"(src));
}
#define CPA_COMMIT() asm volatile("cp.async.commit_group;")
#define CPA_WAIT(N)  asm volatile("cp.async.wait_group %0;" :: "n"(N))

// ---------------- kernel 0a: fp32 -> fp16 inputs + sign masks ----------------
__global__ __launch_bounds__(256) void cvt_inputs(
    const float* __restrict__ q, const float* __restrict__ k) {
    const int wid = threadIdx.x >> 5, lane = threadIdx.x & 31;
    const int row = blockIdx.x * 8 + wid;
    const float* src = blockIdx.y ? k : q;
    u32* dst = blockIdx.y ? g_Xk : g_Xq;
    float* mdst = blockIdx.y ? g_km : g_qm;

    const float4* s4 = reinterpret_cast<const float4*>(src + (size_t)row * ND);
    uint2* d2 = reinterpret_cast<uint2*>(dst + (size_t)row * ND / 2);
    float s = 0.f;
#pragma unroll
    for (int i = 0; i < 4; i++) {
        float4 v = s4[lane + 32 * i];
        s += fabsf(v.x) + fabsf(v.y) + fabsf(v.z) + fabsf(v.w);
        d2[lane + 32 * i] = make_uint2(pack2(v.x, v.y), pack2(v.z, v.w));
    }
#pragma unroll
    for (int o = 16; o; o >>= 1) s += __shfl_xor_sync(0xffffffffu, s, o);
    if (lane == 0) mdst[row] = s > 0.f ? 1.f : 0.f;
}

// ---------------- kernel 0b: fp32 -> fp16 weights ----------------------------
__global__ __launch_bounds__(128) void cvt_w(
    const float* __restrict__ Wq, const float* __restrict__ Wk,
    const float* __restrict__ Wv) {
    const int which = blockIdx.y;
    const float* W = (which == 0) ? Wq : (which == 1) ? Wk : Wv;
    const int row = blockIdx.x, c = threadIdx.x * 4;
    float4 v = *reinterpret_cast<const float4*>(W + (size_t)row * ND + c);
    *reinterpret_cast<uint2*>(&g_Wh[which][((size_t)row * ND + c) >> 1]) =
        make_uint2(pack2(v.x, v.y), pack2(v.z, v.w));
}

// ---------------- kernel 1: fp16 projection GEMMs (3-stage cp.async) ---------
#define PROJ_SMEM (3 * 2 * 128 * 64 * 2)   // 96KB

__global__ __launch_bounds__(256, 2) void proj_kernel(
    const float* __restrict__ bq, const float* __restrict__ bk,
    const float* __restrict__ bv) {
    extern __shared__ char smem_raw[];
    u32* sAu = reinterpret_cast<u32*>(smem_raw);   // [3][4096] u32
    u32* sBu = sAu + 12288;                         // [3][4096] u32
    const u32 sA0 = sptr(sAu), sB0 = sptr(sBu);

    const int which = blockIdx.z;
    const u32* X    = (which == 0) ? g_Xq : g_Xk;
    const u32* Wt   = g_Wh[which];
    const float* bias = (which == 0) ? bq : (which == 1) ? bk : bv;
    u32* out = reinterpret_cast<u32*>((which == 0) ? g_Qh : (which == 1) ? g_Kh : g_Vh);

    const int tid = threadIdx.x, wid = tid >> 5, lane = tid & 31;
    const int g = lane >> 2, tg = lane & 3;
    const int wm = (wid >> 2) * 64, wn = (wid & 3) * 32;
    const int m0 = blockIdx.y * 128, n0 = blockIdx.x * 128;
    const int l7 = lane & 7, mat = lane >> 3;

    auto stage = [&](int buf, int kb) {
#pragma unroll
        for (int j = 0; j < 4; j++) {
            int idx = tid + 256 * j;
            int r = idx >> 3, c = idx & 7;
            u32 off = (u32)(buf * 16384 + (r * 32 + ((c ^ (r & 7)) * 4)) * 4);  // bytes
            cpa16(sA0 + off, X  + (((size_t)(m0 + r) * ND + kb) >> 1) + c * 4);
            cpa16(sB0 + off, Wt + (((size_t)(n0 + r) * ND + kb) >> 1) + c * 4);
        }
    };

    float acc[4][4][4];
#pragma unroll
    for (int mi = 0; mi < 4; mi++)
#pragma unroll
        for (int ni = 0; ni < 4; ni++)
#pragma unroll
            for (int e = 0; e < 4; e++) acc[mi][ni][e] = 0.f;

    stage(0, 0);
    CPA_COMMIT();
    stage(1, 64);
    CPA_COMMIT();

    for (int it = 0; it < 8; it++) {
        const int buf = it % 3;
        if (it == 7) { CPA_WAIT(0); } else { CPA_WAIT(1); }
        __syncthreads();
        if (it + 2 < 8) {
            stage((it + 2) % 3, (it + 2) * 64);
            CPA_COMMIT();
        }

#pragma unroll
        for (int ks = 0; ks < 4; ks++) {
            u32 af[4][4], bf[2][4];
#pragma unroll
            for (int mi = 0; mi < 4; mi++) {
                int row = wm + mi * 16 + (mat & 1) * 8 + l7;
                int chunk = 2 * ks + (mat >> 1);
                ldsm4(af[mi], sA0 + buf * 16384 + row * 128 + ((chunk ^ l7) << 4));
            }
#pragma unroll
            for (int np = 0; np < 2; np++) {
                int nb = (wn >> 3) + 2 * np + (mat >> 1);
                int row = nb * 8 + l7;
                int chunk = 2 * ks + (mat & 1);
                ldsm4(bf[np], sB0 + buf * 16384 + row * 128 + ((chunk ^ l7) << 4));
            }
#pragma unroll
            for (int mi = 0; mi < 4; mi++)
#pragma unroll
                for (int ni = 0; ni < 4; ni++)
                    mma16(acc[mi][ni], af[mi], bf[ni >> 1][(ni & 1) * 2], bf[ni >> 1][(ni & 1) * 2 + 1]);
        }
    }

#pragma unroll
    for (int mi = 0; mi < 4; mi++) {
#pragma unroll
        for (int ni = 0; ni < 4; ni++) {
            int row = m0 + wm + mi * 16 + g;
            int col = n0 + wn + ni * 8 + 2 * tg;
            float2 bv2 = *reinterpret_cast<const float2*>(bias + col);
            out[((size_t)row * ND + col) >> 1] =
                pack2(acc[mi][ni][0] + bv2.x, acc[mi][ni][1] + bv2.y);
            out[((size_t)(row + 8) * ND + col) >> 1] =
                pack2(acc[mi][ni][2] + bv2.x, acc[mi][ni][3] + bv2.y);
        }
    }
}

// ---------------- kernel 2: fp16 flash attention (R12/R14 config + diag skip)
#define ATTN_SMEM (3 * 8192 * 2 + 128 * 4)

__global__ __launch_bounds__(128, 3) void attn_kernel(
    const int* __restrict__ causality, float* __restrict__ outp, int hasW) {
    extern __shared__ char smem_raw[];
    u32* sQu = reinterpret_cast<u32*>(smem_raw);
    u32* sKu = sQu + 4096;
    u32* sVu = sKu + 4096;
    float* sKM = reinterpret_cast<float*>(sVu + 4096);
    const u32 sQ0 = sptr(sQu), sK0 = sptr(sKu), sV0 = sptr(sVu);

    const int qt = 3 - blockIdx.x;          // heavy causal tiles launch first
    const int h = blockIdx.y, b = blockIdx.z;
    const int tid = threadIdx.x, wid = tid >> 5, lane = tid & 31;
    const int g = lane >> 2, tg = lane & 3;
    const int l7 = lane & 7, mat = lane >> 3;
    const int causal = *causality;
    const int q0 = qt * 128;
    const int wm = wid * 32;                // warp owns 32 q-rows

    // ---- stage Q (128 threads, 8 uint4 each) ----
    {
        const uint4* qsrc = g_Qh + (((size_t)(b * NL + q0) * ND + h * NDH) >> 3);
#pragma unroll
        for (int j = 0; j < 8; j++) {
            int idx = tid + 128 * j;
            int r = idx >> 3, c = idx & 7;
            *reinterpret_cast<uint4*>(sQu + r * 32 + ((c ^ (r & 7)) * 4)) = qsrc[r * 64 + c];
        }
    }
    __syncthreads();

    // ---- hoisted Q A-fragments: 2 m-blocks x 4 k-steps ----
    u32 aq[2][4][4];
#pragma unroll
    for (int mb = 0; mb < 2; mb++)
#pragma unroll
        for (int ks = 0; ks < 4; ks++) {
            int row = wm + mb * 16 + (mat & 1) * 8 + l7;
            int chunk = 2 * ks + (mat >> 1);
            ldsm4(aq[mb][ks], sQ0 + row * 128 + ((chunk ^ l7) << 4));
        }

    // per-thread row identities: rows[mb*2 + r] = wm + mb*16 + r*8 + g
    int rowg[4];
    float qm[4];
#pragma unroll
    for (int i = 0; i < 4; i++) {
        rowg[i] = q0 + wm + (i >> 1) * 16 + (i & 1) * 8 + g;
        qm[i] = g_qm[b * NL + rowg[i]];
    }

    float lrun[4] = {0.f, 0.f, 0.f, 0.f};
    const int ktmax = causal ? qt : 3;
    const int wrowmax = q0 + wm + 31;       // warp's max global row (chunk skip)

    float oacc[2][8][4];
#pragma unroll
    for (int mb = 0; mb < 2; mb++)
#pragma unroll
        for (int ni = 0; ni < 8; ni++)
#pragma unroll
            for (int e = 0; e < 4; e++) oacc[mb][ni][e] = 0.f;

    // E scratch row pointers (row = rowg[mb*2], second row at +8*256)
    u32* erow[2];
#pragma unroll
    for (int mb = 0; mb < 2; mb++)
        erow[mb] = g_Eu + ((size_t)(b * NH + h) * NL + rowg[mb * 2]) * 256 + tg;

    for (int kt = 0; kt <= ktmax; kt++) {
        __syncthreads();
        {
            const uint4* kbase = g_Kh + (((size_t)(b * NL + kt * 128) * ND + h * NDH) >> 3);
            const uint4* vbase = g_Vh + (((size_t)(b * NL + kt * 128) * ND + h * NDH) >> 3);
#pragma unroll
            for (int j = 0; j < 8; j++) {
                int idx = tid + 128 * j;
                int r = idx >> 3, c = idx & 7;
                int off = r * 32 + ((c ^ (r & 7)) * 4);
                *reinterpret_cast<uint4*>(sKu + off) = kbase[r * 64 + c];
                *reinterpret_cast<uint4*>(sVu + off) = vbase[r * 64 + c];
            }
            sKM[tid] = g_km[b * NL + kt * 128 + tid];
        }
        __syncthreads();

#pragma unroll
        for (int hf = 0; hf < 2; hf++) {
#pragma unroll
            for (int c = 0; c < 4; c++) {     // 16 kv cols per chunk
                // diagonal-tile chunk skip: whole 16-col window above warp rows.
                // E there is never read (rescale zero-fills col>row without
                // reading) and contributes exact zeros to lrun/oacc.
                if (causal && kt == ktmax && (kt * 128 + hf * 64 + c * 16) > wrowmax)
                    continue;

                // ---- S chunk = Q K^T ----
                float acc[2][2][4];
#pragma unroll
                for (int mb = 0; mb < 2; mb++)
#pragma unroll
                    for (int nb = 0; nb < 2; nb++)
#pragma unroll
                        for (int e = 0; e < 4; e++) acc[mb][nb][e] = 0.f;
#pragma unroll
                for (int ks = 0; ks < 4; ks++) {
                    u32 kb4[4];
                    int row = 64 * hf + (2 * c + (mat >> 1)) * 8 + l7;
                    int chunk = 2 * ks + (mat & 1);
                    ldsm4(kb4, sK0 + row * 128 + ((chunk ^ l7) << 4));
#pragma unroll
                    for (int mb = 0; mb < 2; mb++) {
                        mma16(acc[mb][0], aq[mb][ks], kb4[0], kb4[1]);
                        mma16(acc[mb][1], aq[mb][ks], kb4[2], kb4[3]);
                    }
                }

                // ---- mask, exp2, rowsum, pack, E store ----
                u32 ef[2][4];
#pragma unroll
                for (int mb = 0; mb < 2; mb++) {
#pragma unroll
                    for (int nb = 0; nb < 2; nb++) {
                        int cl = (c * 2 + nb) * 8 + 2 * tg;
                        int cg = kt * 128 + hf * 64 + cl;
                        float km0 = sKM[hf * 64 + cl], km1 = sKM[hf * 64 + cl + 1];
                        float m00 = (causal && (cg     > rowg[mb * 2]))     ? 0.f : km0;
                        float m01 = (causal && (cg + 1 > rowg[mb * 2]))     ? 0.f : km1;
                        float m10 = (causal && (cg     > rowg[mb * 2 + 1])) ? 0.f : km0;
                        float m11 = (causal && (cg + 1 > rowg[mb * 2 + 1])) ? 0.f : km1;
                        float e00 = ex2(fminf(acc[mb][nb][0] * CSCALE, 15.f)) * m00;
                        float e01 = ex2(fminf(acc[mb][nb][1] * CSCALE, 15.f)) * m01;
                        float e10 = ex2(fminf(acc[mb][nb][2] * CSCALE, 15.f)) * m10;
                        float e11 = ex2(fminf(acc[mb][nb][3] * CSCALE, 15.f)) * m11;
                        lrun[mb * 2]     += e00 + e01;
                        lrun[mb * 2 + 1] += e10 + e11;
                        ef[mb][nb * 2]     = pack2(e00, e01);
                        ef[mb][nb * 2 + 1] = pack2(e10, e11);
                    }
                    if (hasW) {
                        u32* e0 = erow[mb] + kt * 64 + hf * 32 + c * 8;
                        e0[0] = ef[mb][0];
                        e0[4] = ef[mb][2];
                        e0[8 * 256]     = ef[mb][1];
                        e0[8 * 256 + 4] = ef[mb][3];
                    }
                }

                // ---- O += E_chunk * V_chunk ----
#pragma unroll
                for (int np = 0; np < 4; np++) {
                    u32 vb4[4];
                    int nb = 2 * np + (mat >> 1);
                    int row = 64 * hf + 16 * c + (mat & 1) * 8 + l7;
                    ldsm4t(vb4, sV0 + row * 128 + ((nb ^ l7) << 4));
#pragma unroll
                    for (int mb = 0; mb < 2; mb++) {
                        mma16(oacc[mb][2 * np],     ef[mb], vb4[0], vb4[1]);
                        mma16(oacc[mb][2 * np + 1], ef[mb], vb4[2], vb4[3]);
                    }
                }
            }
        }
    }

    // reduce partial row-sums across the 4 tg lane-groups
#pragma unroll
    for (int i = 0; i < 4; i++) {
        lrun[i] += __shfl_xor_sync(0xffffffffu, lrun[i], 1);
        lrun[i] += __shfl_xor_sync(0xffffffffu, lrun[i], 2);
    }

    float invl[4];
#pragma unroll
    for (int i = 0; i < 4; i++)
        invl[i] = lrun[i] > 0.f ? qm[i] / lrun[i] : 0.f;
    if (tg == 0) {
#pragma unroll
        for (int i = 0; i < 4; i++)
            g_linv[(b * NH + h) * NL + rowg[i]] = invl[i];
    }

    // ---- O epilogue ----
#pragma unroll
    for (int mb = 0; mb < 2; mb++) {
#pragma unroll
        for (int ni = 0; ni < 8; ni++) {
            int col = h * NDH + ni * 8 + 2 * tg;
            *reinterpret_cast<float2*>(outp + ((size_t)b * NL + rowg[mb * 2]) * ND + col) =
                make_float2(oacc[mb][ni][0] * invl[mb * 2], oacc[mb][ni][1] * invl[mb * 2]);
            *reinterpret_cast<float2*>(outp + ((size_t)b * NL + rowg[mb * 2 + 1]) * ND + col) =
                make_float2(oacc[mb][ni][2] * invl[mb * 2 + 1], oacc[mb][ni][3] * invl[mb * 2 + 1]);
        }
    }
}

// ---------------- kernel 3: normalize fp16 E -> fp32 weights + zero-fill -----
__global__ __launch_bounds__(256) void rescale_kernel(
    const int* __restrict__ causality, float* __restrict__ attnp) {
    const int causal = *causality;
    const int bh = blockIdx.x >> 6;
    const int rblk = blockIdx.x & 63;
    const int row = rblk * 8 + (threadIdx.x >> 5);
    const int lane = threadIdx.x & 31;
    const float linv = g_linv[bh * NL + row];
    const uint2* esrc = reinterpret_cast<const uint2*>(
        g_Eu + ((size_t)bh * NL + row) * 256);
    float* obase = attnp + ((size_t)bh * NL + row) * NL;
#pragma unroll
    for (int j = 0; j < 4; j++) {
        int c4 = lane + 32 * j;
        int col = c4 * 4;
        float4 o;
        if (causal && col > row) {
            o = make_float4(0.f, 0.f, 0.f, 0.f);
        } else {
            uint2 e = esrc[c4];
            float2 lo = __half22float2(*reinterpret_cast<__half2*>(&e.x));
            float2 hi = __half22float2(*reinterpret_cast<__half2*>(&e.y));
            o.x = (causal && col     > row) ? 0.f : lo.x * linv;
            o.y = (causal && col + 1 > row) ? 0.f : lo.y * linv;
            o.z = (causal && col + 2 > row) ? 0.f : hi.x * linv;
            o.w = (causal && col + 3 > row) ? 0.f : hi.y * linv;
        }
        *reinterpret_cast<float4*>(obase + col) = o;
    }
}

// ---------------- launcher ----------------------------------------------------
extern "C" void kernel_launch(void* const* d_in, const int* in_sizes, int n_in,
                              void* d_out, int out_size) {
    (void)in_sizes; (void)n_in;
    const float* queries = (const float*)d_in[0];
    const float* keys    = (const float*)d_in[1];
    const float* Wq = (const float*)d_in[2];
    const float* bq = (const float*)d_in[3];
    const float* Wk = (const float*)d_in[4];
    const float* bk = (const float*)d_in[5];
    const float* Wv = (const float*)d_in[6];
    const float* bv = (const float*)d_in[7];
    const int* caus = (const int*)d_in[8];

    float* outp = (float*)d_out;
    const size_t o_elems = (size_t)NB * NL * ND;
    const size_t a_elems = (size_t)NB * NH * NL * NL;
    float* attnp = ((size_t)out_size >= o_elems + a_elems) ? (outp + o_elems) : nullptr;

    cudaFuncSetAttribute(proj_kernel, cudaFuncAttributeMaxDynamicSharedMemorySize, PROJ_SMEM);
    cudaFuncSetAttribute(attn_kernel, cudaFuncAttributeMaxDynamicSharedMemorySize, ATTN_SMEM);

    cvt_inputs<<<dim3(MTOT / 8, 2), 256>>>(queries, keys);
    cvt_w<<<dim3(ND, 3), 128>>>(Wq, Wk, Wv);
    proj_kernel<<<dim3(4, 128, 3), 256, PROJ_SMEM>>>(bq, bk, bv);
    attn_kernel<<<dim3(4, NH, NB), 128, ATTN_SMEM>>>(caus, outp, attnp != nullptr);
    if (attnp) rescale_kernel<<<NB * NH * 64, 256>>>(caus, attnp);
}